// round 17
// baseline (speedup 1.0000x reference)
#include <cuda_runtime.h>
#include <cuda_bf16.h>
#include <cstdint>

#define IN_F   4096
#define OUT_F  4096
#define NTOK   16384
#define BW     8
#define KW     17          // 2*BW+1
#define NO     4           // outputs per thread
#define NP     9           // packed weight pairs per output
#define WARPS  8           // warps per block (256 threads)
#define GY     256         // token stride / grid.y -> 64 tokens per block
#define WIN_B  576         // 144 floats per warp window
#define TBUF_B 640         // token buffer: 32B guard + 576B data + 32B guard
#define TPS    4           // tokens per slot (per mbarrier)
#define NSLOT  5           // slots per warp
#define SLOT_B (TPS*TBUF_B)           // 2560
#define WPIPE_B (NSLOT*SLOT_B)        // 12800 B per warp
#define PIPE_B  (WARPS*WPIPE_B)       // 102400 B
#define MBAR_OFF PIPE_B
#define NIT    16          // slot-iterations: 16*4 = 64 tokens exactly
#define PDS    3           // slots prefetched ahead (12 tokens in flight)
#define BROWS  (WARPS * 32 * NO)      // 1024 band rows per block
#define WST_F  (BROWS * KW)           // 17408 staged weight floats (69632 B < PIPE_B)
#define SMEM_B (MBAR_OFF + WARPS*NSLOT*8)   // 102720 B

__device__ __forceinline__ void cp4(uint32_t dst_smem, const float* src) {
    asm volatile("cp.async.ca.shared.global [%0], [%1], 4;\n"
                 :: "r"(dst_smem), "l"(src) : "memory");
}
__device__ __forceinline__ void bulk576(uint32_t dst_smem, const float* src, uint32_t mbar) {
    asm volatile("cp.async.bulk.shared::cta.global.mbarrier::complete_tx::bytes "
                 "[%0], [%1], %2, [%3];\n"
                 :: "r"(dst_smem), "l"(src), "r"(576u), "r"(mbar) : "memory");
}
__device__ __forceinline__ void mbar_expect(uint32_t mbar, uint32_t bytes) {
    asm volatile("mbarrier.arrive.expect_tx.shared.b64 _, [%0], %1;\n"
                 :: "r"(mbar), "r"(bytes) : "memory");
}
__device__ __forceinline__ void mbar_wait(uint32_t mbar, uint32_t parity) {
    asm volatile(
        "{\n\t.reg .pred P1;\n\t"
        "WAIT_LOOP_%=:\n\t"
        "mbarrier.try_wait.parity.acquire.cta.shared::cta.b64 P1, [%0], %1, 0x989680;\n\t"
        "@P1 bra.uni WAIT_DONE_%=;\n\t"
        "bra.uni WAIT_LOOP_%=;\n\t"
        "WAIT_DONE_%=:\n\t}"
        :: "r"(mbar), "r"(parity) : "memory");
}

// ---- packed f32x2 helpers (sm_103a) ----
__device__ __forceinline__ uint64_t pk2(float lo, float hi) {
    uint64_t r;
    asm("mov.b64 %0, {%1, %2};" : "=l"(r) : "f"(lo), "f"(hi));
    return r;
}
__device__ __forceinline__ void fma2(uint64_t& d, uint64_t a, uint64_t b) {
    asm("fma.rn.f32x2 %0, %1, %2, %0;" : "+l"(d) : "l"(a), "l"(b));
}
__device__ __forceinline__ void upk2(float& lo, float& hi, uint64_t v) {
    asm("mov.b64 {%0, %1}, %2;" : "=f"(lo), "=f"(hi) : "l"(v));
}

// warp covers 128 consecutive outputs; block covers 1024; grid.x = 4.
__global__ __launch_bounds__(256, 2) void band_linear_kernel(
    const float* __restrict__ x,
    const float* __restrict__ w,
    const float* __restrict__ bias,
    float* __restrict__ out)
{
    extern __shared__ char dsm[];
    float* smw = reinterpret_cast<float*>(dsm);   // weight stage (recycled into pipe)

    const int tid  = threadIdx.x;
    const int warp = tid >> 5;
    const int lane = tid & 31;
    const int wbase  = (blockIdx.x * WARPS + warp) * 128;
    const int o_base = wbase + lane * NO;
    const int win0   = wbase - BW;                // multiple of 4

    const uint32_t smem0   = (uint32_t)__cvta_generic_to_shared(dsm);
    const uint32_t mbar_b  = smem0 + MBAR_OFF + (uint32_t)(warp * NSLOT * 8);
    const uint32_t wpipe   = smem0 + (uint32_t)(warp * WPIPE_B);

    // ---- init this warp's mbarriers (count=1), visible to async proxy ----
    if (lane == 0) {
#pragma unroll
        for (int s = 0; s < NSLOT; ++s)
            asm volatile("mbarrier.init.shared.b64 [%0], 1;\n"
                         :: "r"(mbar_b + (uint32_t)(s * 8)) : "memory");
        asm volatile("fence.proxy.async.shared::cta;\n" ::: "memory");
    }
    __syncwarp();

    // ---- async coalesced weight staging: 1024 rows x 17 taps, one group ----
    {
        const int row0 = blockIdx.x * BROWS;
#pragma unroll
        for (int i = 0; i < WST_F / 256; ++i) {              // 68 cp.async each
            const int e = tid + i * 256;
            const int r = e / KW;
            const int k = e - r * KW;
            const int o = row0 + r;
            int col = o - BW + k;
            col = col < 0 ? 0 : (col >= IN_F ? IN_F - 1 : col);  // clamp; zeroed later
            cp4(smem0 + (uint32_t)(e * 4), w + (long)o * IN_F + col);
        }
        asm volatile("cp.async.commit_group;\ncp.async.wait_group 0;\n" ::: "memory");
    }
    __syncthreads();

    // ---- build PACKED tap-pair weights in registers; smem recycled after ----
    uint64_t wpk[NO][NP];
    uint64_t bp[NO];
    {
        const int rloc = warp * 128 + lane * NO;
#pragma unroll
        for (int oo = 0; oo < NO; ++oo) {
            const int o = o_base + oo;
            bp[oo] = pk2(bias[o], 0.0f);
            const int ms = oo >> 1;
#pragma unroll
            for (int m = 0; m < NP; ++m) {
                const int am  = ms + m;
                const int klo = 2 * am - oo;
                const int khi = klo + 1;
                float vlo = 0.0f, vhi = 0.0f;
                if (klo >= 0 && klo < KW) {
                    const int col = o - BW + klo;
                    const float v = smw[(rloc + oo) * KW + klo];
                    vlo = (col >= 0 && col < IN_F) ? v : 0.0f;
                }
                if (khi >= 0 && khi < KW) {
                    const int col = o - BW + khi;
                    const float v = smw[(rloc + oo) * KW + khi];
                    vhi = (col >= 0 && col < IN_F) ? v : 0.0f;
                }
                wpk[oo][m] = pk2(vlo, vhi);
            }
        }
    }
    __syncthreads();   // all reads of smw done before pipe writes overwrite it

    // ---- zero guard bytes of this warp's 20 token buffers ----
    // Bulk copies write only [32,608); clamped-window warps read up to 32B into
    // a guard and rely on guard*0 == 0 -> guards must be finite.
    {
        char* wp0 = dsm + (size_t)warp * WPIPE_B;
        if (lane < TPS * NSLOT) {        // one token buffer per lane (20 lanes)
            float4 z = make_float4(0.f, 0.f, 0.f, 0.f);
            char* tb = wp0 + (size_t)lane * TBUF_B;
            *reinterpret_cast<float4*>(tb)       = z;
            *reinterpret_cast<float4*>(tb + 16)  = z;
            *reinterpret_cast<float4*>(tb + 608) = z;
            *reinterpret_cast<float4*>(tb + 624) = z;
        }
        __syncwarp();
    }

    // ---- bulk source: clamped window start; consumer compensates via base ----
    int sc = win0;
    sc = sc < 0 ? 0 : (sc > IN_F - 144 ? IN_F - 144 : sc);
    const int dlt   = sc - win0;            // 0, +8 (first warp), -8 (last warp)
    const int cbase = 32 - 4 * dlt;         // consumer byte base inside token buffer

    const int n0 = blockIdx.y;
    const float* xs = x + sc + (long)n0 * IN_F;   // token-0 window source

    // issue slot j (tokens 4j..4j+3): 4 bulks on one mbarrier (lane 0 only)
    auto issue_slot = [&](int j, int sl) {
        if (lane == 0) {
            const uint32_t mb = mbar_b + (uint32_t)(sl * 8);
            mbar_expect(mb, TPS * WIN_B);
            const uint32_t d0 = wpipe + (uint32_t)(sl * SLOT_B) + 32;
            const float* src = xs + (long)(4 * j) * GY * IN_F;
#pragma unroll
            for (int t = 0; t < TPS; ++t)
                bulk576(d0 + (uint32_t)(t * TBUF_B), src + (long)t * GY * IN_F, mb);
        }
    };

    // ---- prologue: slots 0..2 ----
#pragma unroll
    for (int j = 0; j < PDS; ++j) issue_slot(j, j);

    const char* wpc = dsm + (size_t)warp * WPIPE_B;

    int cs = 0, cph = 0;      // consumer slot + phase
    int psl = PDS;            // producer physical slot
    for (int i = 0; i < NIT; ++i) {
        // prefetch slot i+3 (physical slot psl); reuse distance = 2 iterations
        if (i + PDS < NIT) issue_slot(i + PDS, psl);
        if (++psl == NSLOT) psl = 0;

        // wait for slot i
        mbar_wait(mbar_b + (uint32_t)(cs * 8), cph);

        const char* slot = wpc + (size_t)cs * SLOT_B;
        float* orow = out + (long)(n0 + (4 * i) * GY) * OUT_F + o_base;

#pragma unroll
        for (int t = 0; t < TPS; ++t) {
            const char* swp = slot + (size_t)t * TBUF_B;

            // window as 10 native 64-bit pairs: 5 conflict-free LDS.128
            uint64_t xq[10];
#pragma unroll
            for (int c = 0; c < 5; ++c) {
                const ulonglong2 v = *reinterpret_cast<const ulonglong2*>(
                    swp + cbase + (size_t)(lane * NO + 4 * c) * 4);
                xq[2 * c]     = v.x;
                xq[2 * c + 1] = v.y;
            }

            uint64_t acc[NO];
#pragma unroll
            for (int oo = 0; oo < NO; ++oo) {
                acc[oo] = bp[oo];
                const int ms = oo >> 1;
#pragma unroll
                for (int m = 0; m < NP; ++m)
                    fma2(acc[oo], xq[ms + m], wpk[oo][m]);
            }

            float4 o4;
            {
                float lo, hi;
                upk2(lo, hi, acc[0]); o4.x = lo + hi;
                upk2(lo, hi, acc[1]); o4.y = lo + hi;
                upk2(lo, hi, acc[2]); o4.z = lo + hi;
                upk2(lo, hi, acc[3]); o4.w = lo + hi;
            }
            *reinterpret_cast<float4*>(orow) = o4;
            orow += (long)GY * OUT_F;
        }

        if (++cs == NSLOT) { cs = 0; cph ^= 1; }
    }
}

extern "C" void kernel_launch(void* const* d_in, const int* in_sizes, int n_in,
                              void* d_out, int out_size)
{
    const float* x    = (const float*)d_in[0];   // [NTOK, IN_F]
    const float* w    = (const float*)d_in[1];   // [OUT_F, IN_F]
    const float* bias = (const float*)d_in[2];   // [OUT_F]
    float* out = (float*)d_out;

    cudaFuncSetAttribute(band_linear_kernel,
                         cudaFuncAttributeMaxDynamicSharedMemorySize, SMEM_B);

    dim3 grid(OUT_F / BROWS, GY);                // (4, 256)
    dim3 block(WARPS * 32);                      // 256
    band_linear_kernel<<<grid, block, SMEM_B>>>(x, w, bias, out);
}